// round 14
// baseline (speedup 1.0000x reference)
#include <cuda_runtime.h>

// HGCNLayer: KG scatter-mean + sparse user aggregation.
// Inputs (JAX default config: "int64" arrays are int32):
//  0: entity_emb float32 [N_ENT*128], 1: edge_index int32 [2*E],
//  2: edge_type int32 [E], 3: interact_rows int32 [NNZ],
//  4: interact_cols int32 [NNZ], 5: interact_vals float32 [NNZ],
//  (optional n_users scalar), last: weight float32 [R*128]
// Output: [entity_agg (N_ENT*128) | user_agg (N_USR*128)] float32
//
// Counts-first (inline 1/deg; no invert/finalize passes). Scatter kernel is
// latency-bound -> oversubscribed grid + MLP-4. R13 showed regs=48 caps
// occupancy at 5 blocks/SM; this round vectorizes the per-iteration index
// loads (int4/float4, items are consecutive) and applies
// __launch_bounds__(256,6) to reach 6 blocks/SM (75% occ).

#define DD 128
#define MAX_ENTITIES 100000
#define MAX_RELS 32

__device__ float g_counts[MAX_ENTITIES];

__device__ __forceinline__ void red_add_v4(float* p, float4 v) {
    asm volatile("red.global.add.v4.f32 [%0], {%1, %2, %3, %4};"
                 :: "l"(p), "f"(v.x), "f"(v.y), "f"(v.z), "f"(v.w)
                 : "memory");
}

__device__ __forceinline__ void red_add_f32(float* p, float v) {
    asm volatile("red.global.add.f32 [%0], %1;" :: "l"(p), "f"(v) : "memory");
}

// Pass 1: per-head edge counts. int4-vectorized index load, 4 edges/thread.
__global__ void hgcn_count_kernel(const int* __restrict__ edge_index, int n_edges) {
    int t = blockIdx.x * blockDim.x + threadIdx.x;
    int base = t * 4;
    if (base + 3 < n_edges) {
        int4 h = __ldg((const int4*)(edge_index) + t);
        red_add_f32(&g_counts[h.x], 1.0f);
        red_add_f32(&g_counts[h.y], 1.0f);
        red_add_f32(&g_counts[h.z], 1.0f);
        red_add_f32(&g_counts[h.w], 1.0f);
    } else {
        for (int e = base; e < n_edges; e++)
            red_add_f32(&g_counts[edge_index[e]], 1.0f);
    }
}

// Fused scatter kernel, strided warps, oversubscribed grid.
// vec4 == true requires n_edges % 4 == 0 and nnz % 4 == 0.
__global__ void __launch_bounds__(256, 6)
hgcn_scatter_kernel(const float* __restrict__ emb,
                    const int* __restrict__ edge_index,
                    const int* __restrict__ edge_type,
                    const float* __restrict__ weight,
                    const int* __restrict__ rows,
                    const int* __restrict__ cols,
                    const float* __restrict__ vals,
                    float* __restrict__ ent_out,
                    float* __restrict__ user_out,
                    int n_edges, int n_rel, int nnz,
                    int edge_blocks, int user_blocks, int vec4) {
    __shared__ float4 sw[MAX_RELS * 32];
    int lane = threadIdx.x & 31;
    int wib  = threadIdx.x >> 5;
    int wpb  = blockDim.x >> 5;

    if (blockIdx.x < edge_blocks) {
        // ---- edge section: 4 consecutive edges per warp-iteration ----
        int nw4 = n_rel * 32;
        for (int i = threadIdx.x; i < nw4; i += blockDim.x)
            sw[i] = ((const float4*)weight)[i];
        __syncthreads();

        int warp   = blockIdx.x * wpb + wib;
        int nwarps = edge_blocks * wpb;
        long stride = (long)nwarps * 4;

        for (long base = (long)warp * 4; base < n_edges; base += stride) {
            int h[4], t[4], r[4];
            int cnt;
            if (vec4) {
                cnt = 4;
                int4 hv = __ldg((const int4*)(edge_index + base));
                int4 tv = __ldg((const int4*)(edge_index + n_edges + base));
                int4 rv = __ldg((const int4*)(edge_type + base));
                h[0] = hv.x; h[1] = hv.y; h[2] = hv.z; h[3] = hv.w;
                t[0] = tv.x; t[1] = tv.y; t[2] = tv.z; t[3] = tv.w;
                r[0] = rv.x - 1; r[1] = rv.y - 1; r[2] = rv.z - 1; r[3] = rv.w - 1;
            } else {
                cnt = (int)min((long)4, (long)n_edges - base);
                #pragma unroll
                for (int j = 0; j < 4; j++) {
                    long e = base + ((j < cnt) ? j : 0);
                    h[j] = edge_index[e];
                    t[j] = edge_index[n_edges + e];
                    r[j] = edge_type[e] - 1;
                }
            }

            // All gathers in flight before any reduction.
            float4 a[4];
            #pragma unroll
            for (int j = 0; j < 4; j++)
                a[j] = __ldg((const float4*)(emb + (long)t[j] * DD) + lane);

            #pragma unroll
            for (int j = 0; j < 4; j++) {
                if (j < cnt) {
                    float inv = __frcp_rn(fmaxf(g_counts[h[j]], 1.0f));
                    float4 b = sw[r[j] * 32 + lane];
                    float4 v = make_float4(a[j].x * b.x * inv,
                                           a[j].y * b.y * inv,
                                           a[j].z * b.z * inv,
                                           a[j].w * b.w * inv);
                    red_add_v4(ent_out + (long)h[j] * DD + lane * 4, v);
                }
            }
        }
    } else {
        // ---- user section: 4 consecutive nnz per warp-iteration ----
        int warp   = (blockIdx.x - edge_blocks) * wpb + wib;
        int nwarps = user_blocks * wpb;
        long stride = (long)nwarps * 4;

        for (long base = (long)warp * 4; base < nnz; base += stride) {
            int   u[4], c[4];
            float s[4];
            int cnt;
            if (vec4) {
                cnt = 4;
                int4   uv = __ldg((const int4*)(rows + base));
                int4   cv = __ldg((const int4*)(cols + base));
                float4 sv = __ldg((const float4*)(vals + base));
                u[0] = uv.x; u[1] = uv.y; u[2] = uv.z; u[3] = uv.w;
                c[0] = cv.x; c[1] = cv.y; c[2] = cv.z; c[3] = cv.w;
                s[0] = sv.x; s[1] = sv.y; s[2] = sv.z; s[3] = sv.w;
            } else {
                cnt = (int)min((long)4, (long)nnz - base);
                #pragma unroll
                for (int j = 0; j < 4; j++) {
                    long i = base + ((j < cnt) ? j : 0);
                    u[j] = rows[i]; c[j] = cols[i]; s[j] = vals[i];
                }
            }

            float4 a[4];
            #pragma unroll
            for (int j = 0; j < 4; j++)
                a[j] = __ldg((const float4*)(emb + (long)c[j] * DD) + lane);

            #pragma unroll
            for (int j = 0; j < 4; j++) {
                if (j < cnt) {
                    float4 v = make_float4(a[j].x * s[j], a[j].y * s[j],
                                           a[j].z * s[j], a[j].w * s[j]);
                    red_add_v4(user_out + (long)u[j] * DD + lane * 4, v);
                }
            }
        }
    }
}

extern "C" void kernel_launch(void* const* d_in, const int* in_sizes, int n_in,
                              void* d_out, int out_size) {
    const float* emb    = (const float*)d_in[0];
    const int*   ei     = (const int*)d_in[1];
    const int*   et     = (const int*)d_in[2];
    const int*   irows  = (const int*)d_in[3];
    const int*   icols  = (const int*)d_in[4];
    const float* ivals  = (const float*)d_in[5];
    const float* weight = (const float*)d_in[n_in - 1];

    int n_entities = in_sizes[0] / DD;
    int n_edges    = in_sizes[2];
    int nnz        = in_sizes[5];
    int n_rel      = in_sizes[n_in - 1] / DD;
    if (n_rel > MAX_RELS) n_rel = MAX_RELS;

    float* ent_out  = (float*)d_out;
    float* user_out = (float*)d_out + (long)n_entities * DD;

    // Zero output (DMA fill) and counts scratch.
    cudaMemsetAsync(d_out, 0, (size_t)out_size * sizeof(float));
    void* counts_addr = nullptr;
    cudaGetSymbolAddress(&counts_addr, g_counts);
    cudaMemsetAsync(counts_addr, 0, (size_t)n_entities * sizeof(float));

    // Pass 1: counts (int4-vectorized, 4 edges/thread).
    {
        int threads = 256;
        int per_block = threads * 4;
        hgcn_count_kernel<<<(n_edges + per_block - 1) / per_block, threads>>>(ei, n_edges);
    }

    // Fused scatter: oversubscribed grid for latency hiding.
    {
        int threads = 256;        // 8 warps
        int edge_blocks = 1184;   // 8 * 148
        int user_blocks = 1184;
        int vec4 = ((n_edges & 3) == 0 && (nnz & 3) == 0) ? 1 : 0;
        hgcn_scatter_kernel<<<edge_blocks + user_blocks, threads>>>(
            emb, ei, et, weight, irows, icols, ivals,
            ent_out, user_out, n_edges, n_rel, nnz,
            edge_blocks, user_blocks, vec4);
    }
}

// round 15
// speedup vs baseline: 1.2990x; 1.2990x over previous
#include <cuda_runtime.h>

// HGCNLayer: KG scatter-mean + sparse user aggregation — CSR gather version.
// R14 evidence: fp32 red.v4 atomics saturate the LTS atomic path (L2% pinned
// ~61% regardless of occupancy). This version builds a destination-sorted
// permutation (count -> scan -> fill) and assigns ONE WARP PER OUTPUT ROW,
// accumulating in registers and writing each 512B row exactly once. No fp
// atomics remain; only cheap int atomics in count/fill.
//
// Inputs (JAX default x64-off: "int64" arrays are int32):
//  0: entity_emb float32 [N_ENT*128], 1: edge_index int32 [2*E],
//  2: edge_type int32 [E], 3: interact_rows int32 [NNZ],
//  4: interact_cols int32 [NNZ], 5: interact_vals float32 [NNZ],
//  (optional n_users scalar), last: weight float32 [R*128]
// Output: [entity_agg (N_ENT*128) | user_agg (N_USR*128)] float32

#define DD 128
#define MAX_ROWS    160000     // n_entities + n_users (100K + 50K actual)
#define MAX_ITEMS   1700000    // n_edges + nnz (600K + 1M actual)
#define SCAN_BLOCKS 256

__device__ int g_cnt[MAX_ROWS];    // per-destination-row item count
__device__ int g_off[MAX_ROWS];    // exclusive prefix of g_cnt
__device__ int g_cur[MAX_ROWS];    // fill cursors
__device__ int g_perm[MAX_ITEMS];  // item ids grouped by destination row
__device__ int g_bsum[SCAN_BLOCKS];

// ---- pass 1: counts (edges -> rows [0,n_ent), nnz -> rows [n_ent, ...)) ----
__global__ void csr_count_kernel(const int* __restrict__ heads, int n_edges,
                                 const int* __restrict__ urows, int nnz,
                                 int n_ent) {
    int t = blockIdx.x * blockDim.x + threadIdx.x;
    int nthreads = gridDim.x * blockDim.x;
    for (int i = t; i * 4 < n_edges; i += nthreads) {
        int base = i * 4;
        if (base + 3 < n_edges) {
            int4 h = __ldg((const int4*)heads + i);
            atomicAdd(&g_cnt[h.x], 1); atomicAdd(&g_cnt[h.y], 1);
            atomicAdd(&g_cnt[h.z], 1); atomicAdd(&g_cnt[h.w], 1);
        } else {
            for (int e = base; e < n_edges; e++) atomicAdd(&g_cnt[heads[e]], 1);
        }
    }
    for (int i = t; i * 4 < nnz; i += nthreads) {
        int base = i * 4;
        if (base + 3 < nnz) {
            int4 u = __ldg((const int4*)urows + i);
            atomicAdd(&g_cnt[n_ent + u.x], 1); atomicAdd(&g_cnt[n_ent + u.y], 1);
            atomicAdd(&g_cnt[n_ent + u.z], 1); atomicAdd(&g_cnt[n_ent + u.w], 1);
        } else {
            for (int e = base; e < nnz; e++) atomicAdd(&g_cnt[n_ent + urows[e]], 1);
        }
    }
}

// ---- pass 2: 3-step exclusive scan of g_cnt into g_off ----
__global__ void csr_scan1(int n) {   // per-block chunk scan
    __shared__ int sh[256];
    __shared__ int run;
    int chunk = (n + SCAN_BLOCKS - 1) / SCAN_BLOCKS;
    int lo = blockIdx.x * chunk;
    int hi = min(lo + chunk, n);
    if (threadIdx.x == 0) run = 0;
    __syncthreads();
    for (int base = lo; base < hi; base += 256) {
        int i = base + threadIdx.x;
        int v = (i < hi) ? g_cnt[i] : 0;
        sh[threadIdx.x] = v;
        __syncthreads();
        #pragma unroll
        for (int d = 1; d < 256; d <<= 1) {
            int t = (threadIdx.x >= d) ? sh[threadIdx.x - d] : 0;
            __syncthreads();
            sh[threadIdx.x] += t;
            __syncthreads();
        }
        int incl = sh[threadIdx.x];
        if (i < hi) g_off[i] = run + incl - v;
        __syncthreads();
        if (threadIdx.x == 255) run += incl;
        __syncthreads();
    }
    if (threadIdx.x == 0) g_bsum[blockIdx.x] = run;
}

__global__ void csr_scan2() {        // scan the block sums (1 block, 256 thr)
    __shared__ int sh[SCAN_BLOCKS];
    int v = g_bsum[threadIdx.x];
    sh[threadIdx.x] = v;
    __syncthreads();
    #pragma unroll
    for (int d = 1; d < SCAN_BLOCKS; d <<= 1) {
        int t = (threadIdx.x >= d) ? sh[threadIdx.x - d] : 0;
        __syncthreads();
        sh[threadIdx.x] += t;
        __syncthreads();
    }
    g_bsum[threadIdx.x] = sh[threadIdx.x] - v;  // exclusive
}

__global__ void csr_scan3(int n) {   // add block offsets
    int chunk = (n + SCAN_BLOCKS - 1) / SCAN_BLOCKS;
    int i = blockIdx.x * blockDim.x + threadIdx.x;
    if (i < n) g_off[i] += g_bsum[i / chunk];
}

// ---- pass 3: fill permutation ----
__global__ void csr_fill_kernel(const int* __restrict__ heads, int n_edges,
                                const int* __restrict__ urows, int nnz,
                                int n_ent) {
    int t = blockIdx.x * blockDim.x + threadIdx.x;
    int nthreads = gridDim.x * blockDim.x;
    for (int e = t; e < n_edges; e += nthreads) {
        int h = heads[e];
        int slot = g_off[h] + atomicAdd(&g_cur[h], 1);
        g_perm[slot] = e;
    }
    for (int i = t; i < nnz; i += nthreads) {
        int r = n_ent + urows[i];
        int slot = g_off[r] + atomicAdd(&g_cur[r], 1);
        g_perm[slot] = i;
    }
}

// ---- pass 4: aggregate — one warp per output row, register accumulation ----
__global__ void __launch_bounds__(256)
csr_aggregate_kernel(const float* __restrict__ emb,
                     const int* __restrict__ edge_index,
                     const int* __restrict__ edge_type,
                     const float* __restrict__ weight,
                     const int* __restrict__ cols,
                     const float* __restrict__ vals,
                     float* __restrict__ out,       // full output base
                     int n_edges, int n_ent, int n_rows) {
    int warp = blockIdx.x * (blockDim.x >> 5) + (threadIdx.x >> 5);
    if (warp >= n_rows) return;
    int lane = threadIdx.x & 31;

    int s = g_off[warp];
    int c = g_cnt[warp];
    float4 acc = make_float4(0.f, 0.f, 0.f, 0.f);

    if (warp < n_ent) {
        // entity row: acc += emb[tail] * weight[rel], 2-deep pipeline
        for (int k = 0; k < c; k += 2) {
            int e0 = g_perm[s + k];
            bool h1 = (k + 1) < c;
            int e1 = h1 ? g_perm[s + k + 1] : e0;
            int t0 = edge_index[n_edges + e0];
            int r0 = edge_type[e0] - 1;
            int t1 = edge_index[n_edges + e1];
            int r1 = edge_type[e1] - 1;
            float4 a0 = __ldg((const float4*)(emb + (long)t0 * DD) + lane);
            float4 b0 = __ldg((const float4*)(weight + (long)r0 * DD) + lane);
            float4 a1 = __ldg((const float4*)(emb + (long)t1 * DD) + lane);
            float4 b1 = __ldg((const float4*)(weight + (long)r1 * DD) + lane);
            acc.x += a0.x * b0.x; acc.y += a0.y * b0.y;
            acc.z += a0.z * b0.z; acc.w += a0.w * b0.w;
            if (h1) {
                acc.x += a1.x * b1.x; acc.y += a1.y * b1.y;
                acc.z += a1.z * b1.z; acc.w += a1.w * b1.w;
            }
        }
        float inv = 1.0f / fmaxf((float)c, 1.0f);
        acc.x *= inv; acc.y *= inv; acc.z *= inv; acc.w *= inv;
    } else {
        // user row: acc += vals[i] * emb[cols[i]]
        for (int k = 0; k < c; k += 2) {
            int i0 = g_perm[s + k];
            bool h1 = (k + 1) < c;
            int i1 = h1 ? g_perm[s + k + 1] : i0;
            int c0 = cols[i0]; float s0 = vals[i0];
            int c1 = cols[i1]; float s1 = vals[i1];
            float4 a0 = __ldg((const float4*)(emb + (long)c0 * DD) + lane);
            float4 a1 = __ldg((const float4*)(emb + (long)c1 * DD) + lane);
            acc.x += a0.x * s0; acc.y += a0.y * s0;
            acc.z += a0.z * s0; acc.w += a0.w * s0;
            if (h1) {
                acc.x += a1.x * s1; acc.y += a1.y * s1;
                acc.z += a1.z * s1; acc.w += a1.w * s1;
            }
        }
    }
    // one plain 512B store per row; also covers empty rows with zeros
    ((float4*)(out + (long)warp * DD))[lane] = acc;
}

extern "C" void kernel_launch(void* const* d_in, const int* in_sizes, int n_in,
                              void* d_out, int out_size) {
    const float* emb    = (const float*)d_in[0];
    const int*   ei     = (const int*)d_in[1];
    const int*   et     = (const int*)d_in[2];
    const int*   irows  = (const int*)d_in[3];
    const int*   icols  = (const int*)d_in[4];
    const float* ivals  = (const float*)d_in[5];
    const float* weight = (const float*)d_in[n_in - 1];

    int n_entities = in_sizes[0] / DD;
    int n_edges    = in_sizes[2];
    int nnz        = in_sizes[5];
    int n_rows     = out_size / DD;          // n_entities + n_users

    // zero counts + cursors
    void* cnt_addr = nullptr; cudaGetSymbolAddress(&cnt_addr, g_cnt);
    void* cur_addr = nullptr; cudaGetSymbolAddress(&cur_addr, g_cur);
    cudaMemsetAsync(cnt_addr, 0, (size_t)n_rows * sizeof(int));
    cudaMemsetAsync(cur_addr, 0, (size_t)n_rows * sizeof(int));

    // 1) count
    csr_count_kernel<<<592, 256>>>(ei, n_edges, irows, nnz, n_entities);

    // 2) scan (3 steps)
    csr_scan1<<<SCAN_BLOCKS, 256>>>(n_rows);
    csr_scan2<<<1, SCAN_BLOCKS>>>();
    csr_scan3<<<(n_rows + 255) / 256, 256>>>(n_rows);

    // 3) fill permutation
    csr_fill_kernel<<<592, 256>>>(ei, n_edges, irows, nnz, n_entities);

    // 4) aggregate: one warp per output row
    {
        int threads = 256;  // 8 warps
        int blocks = (n_rows + 7) / 8;
        csr_aggregate_kernel<<<blocks, threads>>>(
            emb, ei, et, weight, icols, ivals,
            (float*)d_out, n_edges, n_entities, n_rows);
    }
}

// round 16
// speedup vs baseline: 1.3392x; 1.0309x over previous
#include <cuda_runtime.h>

// HGCNLayer — CSR gather version, payload-permuted.
// count -> scan(2 steps) -> fill(writes payloads into permuted slots) ->
// aggregate (one warp per output row, register accumulation, one store).
// No fp atomics; aggregate's dependent-load chain is payload->emb (2 levels).
//
// Inputs (JAX default x64-off: "int64" arrays are int32):
//  0: entity_emb float32 [N_ENT*128], 1: edge_index int32 [2*E],
//  2: edge_type int32 [E], 3: interact_rows int32 [NNZ],
//  4: interact_cols int32 [NNZ], 5: interact_vals float32 [NNZ],
//  (optional n_users scalar), last: weight float32 [R*128]
// Output: [entity_agg (N_ENT*128) | user_agg (N_USR*128)] float32

#define DD 128
#define MAX_ROWS    160000
#define MAX_ITEMS   1700000
#define SCAN_BLOCKS 256

__device__ int      g_cnt[MAX_ROWS];     // per-row item count
__device__ int      g_off[MAX_ROWS];     // per-chunk exclusive scan
__device__ int      g_cur[MAX_ROWS];     // fill cursors
__device__ int      g_bsum[SCAN_BLOCKS]; // chunk base offsets
__device__ unsigned g_pack[MAX_ITEMS];   // edges: tail|(rel<<20); users: col
__device__ float    g_val[MAX_ITEMS];    // users: val

// ---- pass 1: counts ----
__global__ void csr_count_kernel(const int* __restrict__ heads, int n_edges,
                                 const int* __restrict__ urows, int nnz,
                                 int n_ent) {
    int t = blockIdx.x * blockDim.x + threadIdx.x;
    int nthreads = gridDim.x * blockDim.x;
    for (int i = t; i * 4 < n_edges; i += nthreads) {
        int base = i * 4;
        if (base + 3 < n_edges) {
            int4 h = __ldg((const int4*)heads + i);
            atomicAdd(&g_cnt[h.x], 1); atomicAdd(&g_cnt[h.y], 1);
            atomicAdd(&g_cnt[h.z], 1); atomicAdd(&g_cnt[h.w], 1);
        } else {
            for (int e = base; e < n_edges; e++) atomicAdd(&g_cnt[heads[e]], 1);
        }
    }
    for (int i = t; i * 4 < nnz; i += nthreads) {
        int base = i * 4;
        if (base + 3 < nnz) {
            int4 u = __ldg((const int4*)urows + i);
            atomicAdd(&g_cnt[n_ent + u.x], 1); atomicAdd(&g_cnt[n_ent + u.y], 1);
            atomicAdd(&g_cnt[n_ent + u.z], 1); atomicAdd(&g_cnt[n_ent + u.w], 1);
        } else {
            for (int e = base; e < nnz; e++) atomicAdd(&g_cnt[n_ent + urows[e]], 1);
        }
    }
}

// ---- pass 2: two-step scan (final offset = g_off[i] + g_bsum[i/chunk]) ----
__global__ void csr_scan1(int n) {
    __shared__ int sh[256];
    __shared__ int run;
    int chunk = (n + SCAN_BLOCKS - 1) / SCAN_BLOCKS;
    int lo = blockIdx.x * chunk;
    int hi = min(lo + chunk, n);
    if (threadIdx.x == 0) run = 0;
    __syncthreads();
    for (int base = lo; base < hi; base += 256) {
        int i = base + threadIdx.x;
        int v = (i < hi) ? g_cnt[i] : 0;
        sh[threadIdx.x] = v;
        __syncthreads();
        #pragma unroll
        for (int d = 1; d < 256; d <<= 1) {
            int t = (threadIdx.x >= d) ? sh[threadIdx.x - d] : 0;
            __syncthreads();
            sh[threadIdx.x] += t;
            __syncthreads();
        }
        int incl = sh[threadIdx.x];
        if (i < hi) g_off[i] = run + incl - v;
        __syncthreads();
        if (threadIdx.x == 255) run += incl;
        __syncthreads();
    }
    if (threadIdx.x == 0) g_bsum[blockIdx.x] = run;
}

__global__ void csr_scan2() {
    __shared__ int sh[SCAN_BLOCKS];
    int v = g_bsum[threadIdx.x];
    sh[threadIdx.x] = v;
    __syncthreads();
    #pragma unroll
    for (int d = 1; d < SCAN_BLOCKS; d <<= 1) {
        int t = (threadIdx.x >= d) ? sh[threadIdx.x - d] : 0;
        __syncthreads();
        sh[threadIdx.x] += t;
        __syncthreads();
    }
    g_bsum[threadIdx.x] = sh[threadIdx.x] - v;  // exclusive
}

// ---- pass 3: fill payloads into permuted slots ----
__global__ void csr_fill_kernel(const int* __restrict__ heads,
                                const int* __restrict__ tails,
                                const int* __restrict__ rels,
                                int n_edges,
                                const int* __restrict__ urows,
                                const int* __restrict__ ucols,
                                const float* __restrict__ uvals,
                                int nnz, int n_ent, int chunk) {
    int t = blockIdx.x * blockDim.x + threadIdx.x;
    int nthreads = gridDim.x * blockDim.x;
    for (int e = t; e < n_edges; e += nthreads) {
        int h = heads[e];
        int slot = g_off[h] + g_bsum[h / chunk] + atomicAdd(&g_cur[h], 1);
        g_pack[slot] = (unsigned)tails[e] | ((unsigned)(rels[e] - 1) << 20);
    }
    for (int i = t; i < nnz; i += nthreads) {
        int r = n_ent + urows[i];
        int slot = g_off[r] + g_bsum[r / chunk] + atomicAdd(&g_cur[r], 1);
        g_pack[slot] = (unsigned)ucols[i];
        g_val[slot]  = uvals[i];
    }
}

// ---- pass 4: aggregate — one warp per output row, MLP-4 ----
__global__ void __launch_bounds__(256)
csr_aggregate_kernel(const float* __restrict__ emb,
                     const float* __restrict__ weight,
                     float* __restrict__ out,
                     int n_ent, int n_rows, int chunk) {
    int warp = blockIdx.x * (blockDim.x >> 5) + (threadIdx.x >> 5);
    if (warp >= n_rows) return;
    int lane = threadIdx.x & 31;

    int s = g_off[warp] + g_bsum[warp / chunk];
    int c = g_cnt[warp];
    float4 acc = make_float4(0.f, 0.f, 0.f, 0.f);

    if (warp < n_ent) {
        for (int k = 0; k < c; k += 4) {
            unsigned p[4];
            #pragma unroll
            for (int j = 0; j < 4; j++)
                p[j] = g_pack[s + min(k + j, c - 1)];
            float4 a[4], b[4];
            #pragma unroll
            for (int j = 0; j < 4; j++) {
                int tl = (int)(p[j] & 0xFFFFFu);
                int rl = (int)(p[j] >> 20);
                a[j] = __ldg((const float4*)(emb + (long)tl * DD) + lane);
                b[j] = __ldg((const float4*)(weight + (long)rl * DD) + lane);
            }
            #pragma unroll
            for (int j = 0; j < 4; j++) {
                if (k + j < c) {
                    acc.x += a[j].x * b[j].x; acc.y += a[j].y * b[j].y;
                    acc.z += a[j].z * b[j].z; acc.w += a[j].w * b[j].w;
                }
            }
        }
        float inv = 1.0f / fmaxf((float)c, 1.0f);
        acc.x *= inv; acc.y *= inv; acc.z *= inv; acc.w *= inv;
    } else {
        for (int k = 0; k < c; k += 4) {
            unsigned p[4];
            float    v[4];
            #pragma unroll
            for (int j = 0; j < 4; j++) {
                int idx = s + min(k + j, c - 1);
                p[j] = g_pack[idx];
                v[j] = g_val[idx];
            }
            float4 a[4];
            #pragma unroll
            for (int j = 0; j < 4; j++)
                a[j] = __ldg((const float4*)(emb + (long)p[j] * DD) + lane);
            #pragma unroll
            for (int j = 0; j < 4; j++) {
                if (k + j < c) {
                    acc.x += a[j].x * v[j]; acc.y += a[j].y * v[j];
                    acc.z += a[j].z * v[j]; acc.w += a[j].w * v[j];
                }
            }
        }
    }
    ((float4*)(out + (long)warp * DD))[lane] = acc;
}

extern "C" void kernel_launch(void* const* d_in, const int* in_sizes, int n_in,
                              void* d_out, int out_size) {
    const float* emb    = (const float*)d_in[0];
    const int*   ei     = (const int*)d_in[1];
    const int*   et     = (const int*)d_in[2];
    const int*   irows  = (const int*)d_in[3];
    const int*   icols  = (const int*)d_in[4];
    const float* ivals  = (const float*)d_in[5];
    const float* weight = (const float*)d_in[n_in - 1];

    int n_entities = in_sizes[0] / DD;
    int n_edges    = in_sizes[2];
    int nnz        = in_sizes[5];
    int n_rows     = out_size / DD;
    int chunk      = (n_rows + SCAN_BLOCKS - 1) / SCAN_BLOCKS;

    // zero counts + cursors
    void* cnt_addr = nullptr; cudaGetSymbolAddress(&cnt_addr, g_cnt);
    void* cur_addr = nullptr; cudaGetSymbolAddress(&cur_addr, g_cur);
    cudaMemsetAsync(cnt_addr, 0, (size_t)n_rows * sizeof(int));
    cudaMemsetAsync(cur_addr, 0, (size_t)n_rows * sizeof(int));

    // 1) count
    csr_count_kernel<<<592, 256>>>(ei, n_edges, irows, nnz, n_entities);

    // 2) scan (2 steps; consumers add g_bsum[row/chunk])
    csr_scan1<<<SCAN_BLOCKS, 256>>>(n_rows);
    csr_scan2<<<1, SCAN_BLOCKS>>>();

    // 3) fill payloads
    csr_fill_kernel<<<592, 256>>>(ei, ei + n_edges, et, n_edges,
                                  irows, icols, ivals, nnz, n_entities, chunk);

    // 4) aggregate
    {
        int threads = 256;  // 8 warps
        int blocks = (n_rows + 7) / 8;
        csr_aggregate_kernel<<<blocks, threads>>>(
            emb, weight, (float*)d_out, n_entities, n_rows, chunk);
    }
}

// round 17
// speedup vs baseline: 1.3408x; 1.0011x over previous
#include <cuda_runtime.h>

// HGCNLayer — CSR gather version, payload-permuted.
// count -> scan(2 steps) -> fill(4-wide, payloads into permuted slots) ->
// aggregate (one warp per output row, register accumulation, one store).
// No fp atomics. R16 profile: fill was latency-bound (issue 7.7%) on the
// returning cursor atomicAdd; this round runs 4 independent cursor atomics
// in flight per thread and doubles the grid.
//
// Inputs (JAX default x64-off: "int64" arrays are int32):
//  0: entity_emb float32 [N_ENT*128], 1: edge_index int32 [2*E],
//  2: edge_type int32 [E], 3: interact_rows int32 [NNZ],
//  4: interact_cols int32 [NNZ], 5: interact_vals float32 [NNZ],
//  (optional n_users scalar), last: weight float32 [R*128]
// Output: [entity_agg (N_ENT*128) | user_agg (N_USR*128)] float32

#define DD 128
#define MAX_ROWS    160000
#define MAX_ITEMS   1700000
#define SCAN_BLOCKS 256

__device__ int      g_cnt[MAX_ROWS];     // per-row item count
__device__ int      g_off[MAX_ROWS];     // per-chunk exclusive scan
__device__ int      g_cur[MAX_ROWS];     // fill cursors
__device__ int      g_bsum[SCAN_BLOCKS]; // chunk base offsets
__device__ unsigned g_pack[MAX_ITEMS];   // edges: tail|(rel<<20); users: col
__device__ float    g_val[MAX_ITEMS];    // users: val

// ---- pass 1: counts (4-wide) ----
__global__ void csr_count_kernel(const int* __restrict__ heads, int n_edges,
                                 const int* __restrict__ urows, int nnz,
                                 int n_ent) {
    int t = blockIdx.x * blockDim.x + threadIdx.x;
    int nthreads = gridDim.x * blockDim.x;
    for (int i = t; i * 4 < n_edges; i += nthreads) {
        int base = i * 4;
        if (base + 3 < n_edges) {
            int4 h = __ldg((const int4*)heads + i);
            atomicAdd(&g_cnt[h.x], 1); atomicAdd(&g_cnt[h.y], 1);
            atomicAdd(&g_cnt[h.z], 1); atomicAdd(&g_cnt[h.w], 1);
        } else {
            for (int e = base; e < n_edges; e++) atomicAdd(&g_cnt[heads[e]], 1);
        }
    }
    for (int i = t; i * 4 < nnz; i += nthreads) {
        int base = i * 4;
        if (base + 3 < nnz) {
            int4 u = __ldg((const int4*)urows + i);
            atomicAdd(&g_cnt[n_ent + u.x], 1); atomicAdd(&g_cnt[n_ent + u.y], 1);
            atomicAdd(&g_cnt[n_ent + u.z], 1); atomicAdd(&g_cnt[n_ent + u.w], 1);
        } else {
            for (int e = base; e < nnz; e++) atomicAdd(&g_cnt[n_ent + urows[e]], 1);
        }
    }
}

// ---- pass 2: two-step scan (final offset = g_off[i] + g_bsum[i/chunk]) ----
__global__ void csr_scan1(int n) {
    __shared__ int sh[256];
    __shared__ int run;
    int chunk = (n + SCAN_BLOCKS - 1) / SCAN_BLOCKS;
    int lo = blockIdx.x * chunk;
    int hi = min(lo + chunk, n);
    if (threadIdx.x == 0) run = 0;
    __syncthreads();
    for (int base = lo; base < hi; base += 256) {
        int i = base + threadIdx.x;
        int v = (i < hi) ? g_cnt[i] : 0;
        sh[threadIdx.x] = v;
        __syncthreads();
        #pragma unroll
        for (int d = 1; d < 256; d <<= 1) {
            int t = (threadIdx.x >= d) ? sh[threadIdx.x - d] : 0;
            __syncthreads();
            sh[threadIdx.x] += t;
            __syncthreads();
        }
        int incl = sh[threadIdx.x];
        if (i < hi) g_off[i] = run + incl - v;
        __syncthreads();
        if (threadIdx.x == 255) run += incl;
        __syncthreads();
    }
    if (threadIdx.x == 0) g_bsum[blockIdx.x] = run;
}

__global__ void csr_scan2() {
    __shared__ int sh[SCAN_BLOCKS];
    int v = g_bsum[threadIdx.x];
    sh[threadIdx.x] = v;
    __syncthreads();
    #pragma unroll
    for (int d = 1; d < SCAN_BLOCKS; d <<= 1) {
        int t = (threadIdx.x >= d) ? sh[threadIdx.x - d] : 0;
        __syncthreads();
        sh[threadIdx.x] += t;
        __syncthreads();
    }
    g_bsum[threadIdx.x] = sh[threadIdx.x] - v;  // exclusive
}

// ---- pass 3: fill payloads into permuted slots (4-wide, MLP on atomics) ----
__global__ void csr_fill_kernel(const int* __restrict__ heads,
                                const int* __restrict__ tails,
                                const int* __restrict__ rels,
                                int n_edges,
                                const int* __restrict__ urows,
                                const int* __restrict__ ucols,
                                const float* __restrict__ uvals,
                                int nnz, int n_ent, int chunk) {
    int t = blockIdx.x * blockDim.x + threadIdx.x;
    int nthreads = gridDim.x * blockDim.x;

    for (int i = t; i * 4 < n_edges; i += nthreads) {
        int base = i * 4;
        if (base + 3 < n_edges) {
            int4 h = __ldg((const int4*)heads + i);
            int4 tl = __ldg((const int4*)tails + i);
            int4 rl = __ldg((const int4*)rels + i);
            // 4 independent cursor atomics in flight
            int s0 = atomicAdd(&g_cur[h.x], 1);
            int s1 = atomicAdd(&g_cur[h.y], 1);
            int s2 = atomicAdd(&g_cur[h.z], 1);
            int s3 = atomicAdd(&g_cur[h.w], 1);
            g_pack[g_off[h.x] + g_bsum[h.x / chunk] + s0] =
                (unsigned)tl.x | ((unsigned)(rl.x - 1) << 20);
            g_pack[g_off[h.y] + g_bsum[h.y / chunk] + s1] =
                (unsigned)tl.y | ((unsigned)(rl.y - 1) << 20);
            g_pack[g_off[h.z] + g_bsum[h.z / chunk] + s2] =
                (unsigned)tl.z | ((unsigned)(rl.z - 1) << 20);
            g_pack[g_off[h.w] + g_bsum[h.w / chunk] + s3] =
                (unsigned)tl.w | ((unsigned)(rl.w - 1) << 20);
        } else {
            for (int e = base; e < n_edges; e++) {
                int h = heads[e];
                int slot = g_off[h] + g_bsum[h / chunk] + atomicAdd(&g_cur[h], 1);
                g_pack[slot] = (unsigned)tails[e] | ((unsigned)(rels[e] - 1) << 20);
            }
        }
    }

    for (int i = t; i * 4 < nnz; i += nthreads) {
        int base = i * 4;
        if (base + 3 < nnz) {
            int4   r = __ldg((const int4*)urows + i);
            int4   c = __ldg((const int4*)ucols + i);
            float4 v = __ldg((const float4*)uvals + i);
            int r0 = n_ent + r.x, r1 = n_ent + r.y,
                r2 = n_ent + r.z, r3 = n_ent + r.w;
            int s0 = atomicAdd(&g_cur[r0], 1);
            int s1 = atomicAdd(&g_cur[r1], 1);
            int s2 = atomicAdd(&g_cur[r2], 1);
            int s3 = atomicAdd(&g_cur[r3], 1);
            int p0 = g_off[r0] + g_bsum[r0 / chunk] + s0;
            int p1 = g_off[r1] + g_bsum[r1 / chunk] + s1;
            int p2 = g_off[r2] + g_bsum[r2 / chunk] + s2;
            int p3 = g_off[r3] + g_bsum[r3 / chunk] + s3;
            g_pack[p0] = (unsigned)c.x; g_val[p0] = v.x;
            g_pack[p1] = (unsigned)c.y; g_val[p1] = v.y;
            g_pack[p2] = (unsigned)c.z; g_val[p2] = v.z;
            g_pack[p3] = (unsigned)c.w; g_val[p3] = v.w;
        } else {
            for (int e = base; e < nnz; e++) {
                int r = n_ent + urows[e];
                int slot = g_off[r] + g_bsum[r / chunk] + atomicAdd(&g_cur[r], 1);
                g_pack[slot] = (unsigned)ucols[e];
                g_val[slot]  = uvals[e];
            }
        }
    }
}

// ---- pass 4: aggregate — one warp per output row, MLP-4 ----
__global__ void __launch_bounds__(256)
csr_aggregate_kernel(const float* __restrict__ emb,
                     const float* __restrict__ weight,
                     float* __restrict__ out,
                     int n_ent, int n_rows, int chunk) {
    int warp = blockIdx.x * (blockDim.x >> 5) + (threadIdx.x >> 5);
    if (warp >= n_rows) return;
    int lane = threadIdx.x & 31;

    int s = g_off[warp] + g_bsum[warp / chunk];
    int c = g_cnt[warp];
    float4 acc = make_float4(0.f, 0.f, 0.f, 0.f);

    if (warp < n_ent) {
        for (int k = 0; k < c; k += 4) {
            unsigned p[4];
            #pragma unroll
            for (int j = 0; j < 4; j++)
                p[j] = g_pack[s + min(k + j, c - 1)];
            float4 a[4], b[4];
            #pragma unroll
            for (int j = 0; j < 4; j++) {
                int tl = (int)(p[j] & 0xFFFFFu);
                int rl = (int)(p[j] >> 20);
                a[j] = __ldg((const float4*)(emb + (long)tl * DD) + lane);
                b[j] = __ldg((const float4*)(weight + (long)rl * DD) + lane);
            }
            #pragma unroll
            for (int j = 0; j < 4; j++) {
                if (k + j < c) {
                    acc.x += a[j].x * b[j].x; acc.y += a[j].y * b[j].y;
                    acc.z += a[j].z * b[j].z; acc.w += a[j].w * b[j].w;
                }
            }
        }
        float inv = 1.0f / fmaxf((float)c, 1.0f);
        acc.x *= inv; acc.y *= inv; acc.z *= inv; acc.w *= inv;
    } else {
        for (int k = 0; k < c; k += 4) {
            unsigned p[4];
            float    v[4];
            #pragma unroll
            for (int j = 0; j < 4; j++) {
                int idx = s + min(k + j, c - 1);
                p[j] = g_pack[idx];
                v[j] = g_val[idx];
            }
            float4 a[4];
            #pragma unroll
            for (int j = 0; j < 4; j++)
                a[j] = __ldg((const float4*)(emb + (long)p[j] * DD) + lane);
            #pragma unroll
            for (int j = 0; j < 4; j++) {
                if (k + j < c) {
                    acc.x += a[j].x * v[j]; acc.y += a[j].y * v[j];
                    acc.z += a[j].z * v[j]; acc.w += a[j].w * v[j];
                }
            }
        }
    }
    ((float4*)(out + (long)warp * DD))[lane] = acc;
}

extern "C" void kernel_launch(void* const* d_in, const int* in_sizes, int n_in,
                              void* d_out, int out_size) {
    const float* emb    = (const float*)d_in[0];
    const int*   ei     = (const int*)d_in[1];
    const int*   et     = (const int*)d_in[2];
    const int*   irows  = (const int*)d_in[3];
    const int*   icols  = (const int*)d_in[4];
    const float* ivals  = (const float*)d_in[5];
    const float* weight = (const float*)d_in[n_in - 1];

    int n_entities = in_sizes[0] / DD;
    int n_edges    = in_sizes[2];
    int nnz        = in_sizes[5];
    int n_rows     = out_size / DD;
    int chunk      = (n_rows + SCAN_BLOCKS - 1) / SCAN_BLOCKS;

    // zero counts + cursors
    void* cnt_addr = nullptr; cudaGetSymbolAddress(&cnt_addr, g_cnt);
    void* cur_addr = nullptr; cudaGetSymbolAddress(&cur_addr, g_cur);
    cudaMemsetAsync(cnt_addr, 0, (size_t)n_rows * sizeof(int));
    cudaMemsetAsync(cur_addr, 0, (size_t)n_rows * sizeof(int));

    // 1) count
    csr_count_kernel<<<1184, 256>>>(ei, n_edges, irows, nnz, n_entities);

    // 2) scan (2 steps; consumers add g_bsum[row/chunk])
    csr_scan1<<<SCAN_BLOCKS, 256>>>(n_rows);
    csr_scan2<<<1, SCAN_BLOCKS>>>();

    // 3) fill payloads (4-wide, MLP on cursor atomics)
    csr_fill_kernel<<<1184, 256>>>(ei, ei + n_edges, et, n_edges,
                                   irows, icols, ivals, nnz, n_entities, chunk);

    // 4) aggregate
    {
        int threads = 256;  // 8 warps
        int blocks = (n_rows + 7) / 8;
        csr_aggregate_kernel<<<blocks, threads>>>(
            emb, weight, (float*)d_out, n_entities, n_rows, chunk);
    }
}